// round 15
// baseline (speedup 1.0000x reference)
#include <cuda_runtime.h>
#include <cuda_bf16.h>
#include <cuda_fp16.h>
#include <cstdint>

// Problem dims
#define BB  2
#define SS  2048
#define HH  1024
#define NHH 16
#define HDD 64
#define MM  (BB*SS)          // 4096 rows

// ---------------- scratch (no cudaMalloc allowed) ----------------
__device__ __nv_bfloat16 g_a2[MM * 2048];        // bf16 hi|lo split activations
__device__ __half        g_ah[MM * 1024];        // fp16 single activations / attn out
__device__ __nv_bfloat16 g_wq2[HH * 2048];
__device__ __nv_bfloat16 g_wk2[HH * 2048];
__device__ __half        g_wvh[HH * 2048];       // fp16 split
__device__ __half        g_woh[HH * 2048];
__device__ __nv_bfloat16 g_q2[MM * 2048];        // per-head split [row][h*128+(hi|lo)]
__device__ __nv_bfloat16 g_k2[MM * 2048];
__device__ __half g_vh[MM * 1024];               // fp16 single per-head [row][h*64+d]

// ================= PTX helpers =================
__device__ __forceinline__ uint32_t smem_u32(const void* p) {
    uint32_t a;
    asm("{ .reg .u64 t; cvta.to.shared.u64 t, %1; cvt.u32.u64 %0, t; }" : "=r"(a) : "l"(p));
    return a;
}
__device__ __forceinline__ void cp16(uint32_t dst, const void* src) {
    asm volatile("cp.async.cg.shared.global [%0], [%1], 16;" :: "r"(dst), "l"(src));
}
__device__ __forceinline__ void cp_commit() {
    asm volatile("cp.async.commit_group;" ::: "memory");
}
template<int N> __device__ __forceinline__ void cp_wait() {
    asm volatile("cp.async.wait_group %0;" :: "n"(N) : "memory");
}
__device__ __forceinline__ void ldmat4(uint32_t& r0, uint32_t& r1, uint32_t& r2, uint32_t& r3,
                                       uint32_t addr) {
    asm volatile("ldmatrix.sync.aligned.m8n8.x4.shared.b16 {%0,%1,%2,%3}, [%4];"
                 : "=r"(r0), "=r"(r1), "=r"(r2), "=r"(r3) : "r"(addr));
}
__device__ __forceinline__ void ldmat4t(uint32_t& r0, uint32_t& r1, uint32_t& r2, uint32_t& r3,
                                        uint32_t addr) {
    asm volatile("ldmatrix.sync.aligned.m8n8.x4.trans.shared.b16 {%0,%1,%2,%3}, [%4];"
                 : "=r"(r0), "=r"(r1), "=r"(r2), "=r"(r3) : "r"(addr));
}
__device__ __forceinline__ void mma16816(float* d, uint32_t a0, uint32_t a1, uint32_t a2,
                                         uint32_t a3, uint32_t b0, uint32_t b1) {
    asm volatile("mma.sync.aligned.m16n8k16.row.col.f32.bf16.bf16.f32 "
                 "{%0,%1,%2,%3},{%4,%5,%6,%7},{%8,%9},{%0,%1,%2,%3};"
                 : "+f"(d[0]), "+f"(d[1]), "+f"(d[2]), "+f"(d[3])
                 : "r"(a0), "r"(a1), "r"(a2), "r"(a3), "r"(b0), "r"(b1));
}
__device__ __forceinline__ void mma16816h(float* d, uint32_t a0, uint32_t a1, uint32_t a2,
                                          uint32_t a3, uint32_t b0, uint32_t b1) {
    asm volatile("mma.sync.aligned.m16n8k16.row.col.f32.f16.f16.f32 "
                 "{%0,%1,%2,%3},{%4,%5,%6,%7},{%8,%9},{%0,%1,%2,%3};"
                 : "+f"(d[0]), "+f"(d[1]), "+f"(d[2]), "+f"(d[3])
                 : "r"(a0), "r"(a1), "r"(a2), "r"(a3), "r"(b0), "r"(b1));
}
__device__ __forceinline__ uint32_t pack_h2(float x, float y) {
    __half2 t = __floats2half2_rn(x, y);
    return *(uint32_t*)&t;
}

// ================= fused prep =================
__device__ __forceinline__ void split_bf(const float* __restrict__ a,
                                         const float* __restrict__ b,
                                         __nv_bfloat16* __restrict__ out, int i) {
    int r = i >> 8;
    int c4 = (i & 255) << 2;
    float4 x = ((const float4*)a)[i];
    if (b) {
        float4 y = ((const float4*)b)[i];
        x.x += y.x; x.y += y.y; x.z += y.z; x.w += y.w;
    }
    float vf[4] = {x.x, x.y, x.z, x.w};
    __nv_bfloat16 h[4], l[4];
#pragma unroll
    for (int j = 0; j < 4; j++) {
        h[j] = __float2bfloat16_rn(vf[j]);
        l[j] = __float2bfloat16_rn(vf[j] - __bfloat162float(h[j]));
    }
    __nv_bfloat16* o = out + (size_t)r * 2048 + c4;
    ((__nv_bfloat162*)o)[0] = __halves2bfloat162(h[0], h[1]);
    ((__nv_bfloat162*)o)[1] = __halves2bfloat162(h[2], h[3]);
    ((__nv_bfloat162*)(o + 1024))[0] = __halves2bfloat162(l[0], l[1]);
    ((__nv_bfloat162*)(o + 1024))[1] = __halves2bfloat162(l[2], l[3]);
}

__device__ __forceinline__ void split_h(const float* __restrict__ a,
                                        const float* __restrict__ b,
                                        __half* __restrict__ out, int i) {
    int r = i >> 8;
    int c4 = (i & 255) << 2;
    float4 x = ((const float4*)a)[i];
    float4 y = ((const float4*)b)[i];
    x.x += y.x; x.y += y.y; x.z += y.z; x.w += y.w;
    float vf[4] = {x.x, x.y, x.z, x.w};
    __half h[4], l[4];
#pragma unroll
    for (int j = 0; j < 4; j++) {
        h[j] = __float2half_rn(vf[j]);
        l[j] = __float2half_rn(vf[j] - __half2float(h[j]));
    }
    __half* o = out + (size_t)r * 2048 + c4;
    ((__half2*)o)[0] = __halves2half2(h[0], h[1]);
    ((__half2*)o)[1] = __halves2half2(h[2], h[3]);
    ((__half2*)(o + 1024))[0] = __halves2half2(l[0], l[1]);
    ((__half2*)(o + 1024))[1] = __halves2half2(l[2], l[3]);
}

__global__ void prep_kernel(const float* __restrict__ hid,
                            const float* __restrict__ s0, const float* __restrict__ d0,
                            const float* __restrict__ s1, const float* __restrict__ d1,
                            const float* __restrict__ s2, const float* __restrict__ d2,
                            const float* __restrict__ s3, const float* __restrict__ d3,
                            __nv_bfloat16* __restrict__ oa, __half* __restrict__ oah,
                            __nv_bfloat16* __restrict__ o0, __nv_bfloat16* __restrict__ o1,
                            __half* __restrict__ o2, __half* __restrict__ o3) {
    const int y = blockIdx.y;
    const int base = blockIdx.x * 256 + threadIdx.x;
    if (y == 4) {
#pragma unroll
        for (int k = 0; k < 4; k++) {
            const int i = base + k * 262144;
            split_bf(hid, nullptr, oa, i);
            float4 x = ((const float4*)hid)[i];
            int r = i >> 8, c4 = (i & 255) << 2;
            __half* o = oah + (size_t)r * 1024 + c4;
            ((__half2*)o)[0] = __floats2half2_rn(x.x, x.y);
            ((__half2*)o)[1] = __floats2half2_rn(x.z, x.w);
        }
    } else if (y == 0) split_bf(s0, d0, o0, base);
    else if (y == 1) split_bf(s1, d1, o1, base);
    else if (y == 2) split_h(s2, d2, o2, base);
    else             split_h(s3, d3, o3, base);
}

// ================= GEMM common =================
#define GROWB 144
#define GATILE (256 * GROWB)             // 36864
#define GBTILE (128 * GROWB)             // 18432
#define GSTAGEB (GATILE + GBTILE)        // 55296
#define GSMEM4 (4 * GSTAGEB)             // 221184
#define GNCH 48                          // bf16: 3 terms x 16
#define HNCH 32                          // fp16: 2 terms x 16

// ================= merged projection kernel: z=0,1 bf16 QK; z=2 fp16 V =================
__global__ __launch_bounds__(512, 1)
void tc_proj(const __nv_bfloat16* __restrict__ A2,
             const __nv_bfloat16* __restrict__ W2q,
             const __nv_bfloat16* __restrict__ W2k,
             const __half* __restrict__ Ah,
             const __half* __restrict__ Wvh,
             __nv_bfloat16* __restrict__ Oq, __nv_bfloat16* __restrict__ Ok,
             __half* __restrict__ Ov) {
    extern __shared__ __align__(128) char smbuf[];
    const uint32_t sbase = smem_u32(smbuf);

    const int tid = threadIdx.x;
    const int wid = tid >> 5;
    const int lane = tid & 31;
    const int m0 = blockIdx.y * 256;
    const int n0 = blockIdx.x * 128;

    const int tAr = tid >> 1, tAh = tid & 1;
    const int tBr = tid >> 2, tBq = tid & 3;
    const uint32_t sdA0 = sbase + tAr * GROWB + tAh * 64;
    const uint32_t sdB0 = sbase + GATILE + tBr * GROWB + tBq * 32;

    const int mi = lane >> 3, rr = lane & 7;
    const int lmrow = (mi & 1) * 8 + rr;
    const int lmunit = (mi >> 1);
    const int wm = wid >> 2;
    const int wn = wid & 3;
    const int g = lane >> 2, it = lane & 3;

    float acc[4][4][4];
#pragma unroll
    for (int am = 0; am < 4; am++)
#pragma unroll
        for (int bn = 0; bn < 4; bn++)
#pragma unroll
            for (int j = 0; j < 4; j++) acc[am][bn][j] = 0.f;

    if (blockIdx.z < 2) {
        // ---------------- bf16 3-term path ----------------
        const __nv_bfloat16* W2 = (blockIdx.z == 0) ? W2q : W2k;
        __nv_bfloat16* OUT = (blockIdx.z == 0) ? Oq : Ok;
        const __nv_bfloat16* gA = A2 + (size_t)(m0 + tAr) * 2048 + tAh * 32;
        const __nv_bfloat16* gB = W2 + (size_t)(n0 + tBr) * 2048 + tBq * 16;
        const int offA[3] = { 0, 0, 1024 };
        const int offB[3] = { 0, 1024, 0 };

#pragma unroll
        for (int p = 0; p < 3; p++) {
            const __nv_bfloat16* sAg = gA + offA[0] + p * 64;
            const __nv_bfloat16* sBg = gB + offB[0] + p * 64;
            const uint32_t dA = sdA0 + p * GSTAGEB;
            const uint32_t dB = sdB0 + p * GSTAGEB;
#pragma unroll
            for (int q = 0; q < 4; q++) cp16(dA + q * 16, sAg + q * 8);
#pragma unroll
            for (int q = 0; q < 2; q++) cp16(dB + q * 16, sBg + q * 8);
            cp_commit();
        }

        for (int c = 0; c < GNCH; ++c) {
            if (c + 2 < GNCH) cp_wait<2>();
            else if (c + 1 < GNCH) cp_wait<1>();
            else cp_wait<0>();
            __syncthreads();

            if (c + 3 < GNCH) {
                const int cn = c + 3;
                const int t = cn >> 4, kc = cn & 15;
                const __nv_bfloat16* sAg = gA + offA[t] + kc * 64;
                const __nv_bfloat16* sBg = gB + offB[t] + kc * 64;
                const uint32_t dA = sdA0 + (uint32_t)(cn & 3) * GSTAGEB;
                const uint32_t dB = sdB0 + (uint32_t)(cn & 3) * GSTAGEB;
#pragma unroll
                for (int q = 0; q < 4; q++) cp16(dA + q * 16, sAg + q * 8);
#pragma unroll
                for (int q = 0; q < 2; q++) cp16(dB + q * 16, sBg + q * 8);
                cp_commit();
            }

            const uint32_t sA = sbase + (uint32_t)(c & 3) * GSTAGEB;
            const uint32_t sB = sA + GATILE;
#pragma unroll
            for (int kb = 0; kb < 4; kb++) {
                uint32_t a[4][4];
#pragma unroll
                for (int am = 0; am < 4; am++)
                    ldmat4(a[am][0], a[am][1], a[am][2], a[am][3],
                           sA + (wm * 64 + am * 16 + lmrow) * GROWB + (kb * 2 + lmunit) * 16);
#pragma unroll
                for (int bb2 = 0; bb2 < 2; bb2++) {
                    uint32_t r0, r1, r2, r3;
                    ldmat4(r0, r1, r2, r3,
                           sB + (wn * 32 + bb2 * 16 + lmrow) * GROWB + (kb * 2 + lmunit) * 16);
#pragma unroll
                    for (int am = 0; am < 4; am++) {
                        mma16816(acc[am][bb2 * 2],     a[am][0], a[am][1], a[am][2], a[am][3], r0, r2);
                        mma16816(acc[am][bb2 * 2 + 1], a[am][0], a[am][1], a[am][2], a[am][3], r1, r3);
                    }
                }
            }
        }

#pragma unroll
        for (int am = 0; am < 4; am++) {
            const int row0 = m0 + wm * 64 + am * 16 + g;
#pragma unroll
            for (int bn = 0; bn < 4; bn++) {
                const int col = n0 + wn * 32 + bn * 8 + it * 2;
                const int h = col >> 6, d = col & 63;
#pragma unroll
                for (int half_i = 0; half_i < 2; half_i++) {
                    float v0 = acc[am][bn][half_i * 2], v1 = acc[am][bn][half_i * 2 + 1];
                    __nv_bfloat16 h0 = __float2bfloat16_rn(v0);
                    __nv_bfloat16 h1 = __float2bfloat16_rn(v1);
                    __nv_bfloat162 hi2; hi2.x = h0; hi2.y = h1;
                    __nv_bfloat162 lo2;
                    lo2.x = __float2bfloat16_rn(v0 - __bfloat162float(h0));
                    lo2.y = __float2bfloat16_rn(v1 - __bfloat162float(h1));
                    __nv_bfloat16* op = OUT + (size_t)(row0 + half_i * 8) * 2048 + h * 128 + d;
                    *(__nv_bfloat162*)op = hi2;
                    *(__nv_bfloat162*)(op + 64) = lo2;
                }
            }
        }
    } else {
        // ---------------- fp16 2-term path (V) ----------------
        const __half* gA = Ah + (size_t)(m0 + tAr) * 1024 + tAh * 32;
        const __half* gB = Wvh + (size_t)(n0 + tBr) * 2048 + tBq * 16;

#pragma unroll
        for (int p = 0; p < 3; p++) {
            const __half* sAg = gA + p * 64;
            const __half* sBg = gB + p * 64;
            const uint32_t dA = sdA0 + p * GSTAGEB;
            const uint32_t dB = sdB0 + p * GSTAGEB;
#pragma unroll
            for (int q = 0; q < 4; q++) cp16(dA + q * 16, sAg + q * 8);
#pragma unroll
            for (int q = 0; q < 2; q++) cp16(dB + q * 16, sBg + q * 8);
            cp_commit();
        }

        for (int c = 0; c < HNCH; ++c) {
            if (c + 2 < HNCH) cp_wait<2>();
            else if (c + 1 < HNCH) cp_wait<1>();
            else cp_wait<0>();
            __syncthreads();

            if (c + 3 < HNCH) {
                const int cn = c + 3;
                const int t = cn >> 4, kc = cn & 15;
                const __half* sAg = gA + kc * 64;
                const __half* sBg = gB + t * 1024 + kc * 64;
                const uint32_t dA = sdA0 + (uint32_t)(cn & 3) * GSTAGEB;
                const uint32_t dB = sdB0 + (uint32_t)(cn & 3) * GSTAGEB;
#pragma unroll
                for (int q = 0; q < 4; q++) cp16(dA + q * 16, sAg + q * 8);
#pragma unroll
                for (int q = 0; q < 2; q++) cp16(dB + q * 16, sBg + q * 8);
                cp_commit();
            }

            const uint32_t sA = sbase + (uint32_t)(c & 3) * GSTAGEB;
            const uint32_t sB = sA + GATILE;
#pragma unroll
            for (int kb = 0; kb < 4; kb++) {
                uint32_t a[4][4];
#pragma unroll
                for (int am = 0; am < 4; am++)
                    ldmat4(a[am][0], a[am][1], a[am][2], a[am][3],
                           sA + (wm * 64 + am * 16 + lmrow) * GROWB + (kb * 2 + lmunit) * 16);
#pragma unroll
                for (int bb2 = 0; bb2 < 2; bb2++) {
                    uint32_t r0, r1, r2, r3;
                    ldmat4(r0, r1, r2, r3,
                           sB + (wn * 32 + bb2 * 16 + lmrow) * GROWB + (kb * 2 + lmunit) * 16);
#pragma unroll
                    for (int am = 0; am < 4; am++) {
                        mma16816h(acc[am][bb2 * 2],     a[am][0], a[am][1], a[am][2], a[am][3], r0, r2);
                        mma16816h(acc[am][bb2 * 2 + 1], a[am][0], a[am][1], a[am][2], a[am][3], r1, r3);
                    }
                }
            }
        }

#pragma unroll
        for (int am = 0; am < 4; am++) {
            const int row0 = m0 + wm * 64 + am * 16 + g;
#pragma unroll
            for (int bn = 0; bn < 4; bn++) {
                const int col = n0 + wn * 32 + bn * 8 + it * 2;
                const int h = col >> 6, d = col & 63;
#pragma unroll
                for (int half_i = 0; half_i < 2; half_i++) {
                    __half2 hv = __floats2half2_rn(acc[am][bn][half_i * 2],
                                                   acc[am][bn][half_i * 2 + 1]);
                    __half* op = Ov + (size_t)(row0 + half_i * 8) * 1024 + h * 64 + d;
                    *(__half2*)op = hv;
                }
            }
        }
    }
}

// ================= O projection: fp16 2-term, fp32 out (4-stage) =================
__global__ __launch_bounds__(512, 1)
void tc_gemm_o(const __half* __restrict__ Ah,
               const __half* __restrict__ Wh,
               float* __restrict__ OUT) {
    extern __shared__ __align__(128) char smbuf[];
    const uint32_t sbase = smem_u32(smbuf);

    const int tid = threadIdx.x;
    const int wid = tid >> 5;
    const int lane = tid & 31;
    const int m0 = blockIdx.y * 256;
    const int n0 = blockIdx.x * 128;

    const int tAr = tid >> 1, tAh = tid & 1;
    const int tBr = tid >> 2, tBq = tid & 3;
    const __half* gA = Ah + (size_t)(m0 + tAr) * 1024 + tAh * 32;
    const __half* gB = Wh + (size_t)(n0 + tBr) * 2048 + tBq * 16;
    const uint32_t sdA0 = sbase + tAr * GROWB + tAh * 64;
    const uint32_t sdB0 = sbase + GATILE + tBr * GROWB + tBq * 32;

    const int mi = lane >> 3, rr = lane & 7;
    const int lmrow = (mi & 1) * 8 + rr;
    const int lmunit = (mi >> 1);
    const int wm = wid >> 2;
    const int wn = wid & 3;

    float acc[4][4][4];
#pragma unroll
    for (int am = 0; am < 4; am++)
#pragma unroll
        for (int bn = 0; bn < 4; bn++)
#pragma unroll
            for (int j = 0; j < 4; j++) acc[am][bn][j] = 0.f;

#pragma unroll
    for (int p = 0; p < 3; p++) {
        const __half* sAg = gA + p * 64;
        const __half* sBg = gB + p * 64;
        const uint32_t dA = sdA0 + p * GSTAGEB;
        const uint32_t dB = sdB0 + p * GSTAGEB;
#pragma unroll
        for (int q = 0; q < 4; q++) cp16(dA + q * 16, sAg + q * 8);
#pragma unroll
        for (int q = 0; q < 2; q++) cp16(dB + q * 16, sBg + q * 8);
        cp_commit();
    }

    for (int c = 0; c < HNCH; ++c) {
        if (c + 2 < HNCH) cp_wait<2>();
        else if (c + 1 < HNCH) cp_wait<1>();
        else cp_wait<0>();
        __syncthreads();

        if (c + 3 < HNCH) {
            const int cn = c + 3;
            const int t = cn >> 4, kc = cn & 15;
            const __half* sAg = gA + kc * 64;
            const __half* sBg = gB + t * 1024 + kc * 64;
            const uint32_t dA = sdA0 + (uint32_t)(cn & 3) * GSTAGEB;
            const uint32_t dB = sdB0 + (uint32_t)(cn & 3) * GSTAGEB;
#pragma unroll
            for (int q = 0; q < 4; q++) cp16(dA + q * 16, sAg + q * 8);
#pragma unroll
            for (int q = 0; q < 2; q++) cp16(dB + q * 16, sBg + q * 8);
            cp_commit();
        }

        const uint32_t sA = sbase + (uint32_t)(c & 3) * GSTAGEB;
        const uint32_t sB = sA + GATILE;
#pragma unroll
        for (int kb = 0; kb < 4; kb++) {
            uint32_t a[4][4];
#pragma unroll
            for (int am = 0; am < 4; am++)
                ldmat4(a[am][0], a[am][1], a[am][2], a[am][3],
                       sA + (wm * 64 + am * 16 + lmrow) * GROWB + (kb * 2 + lmunit) * 16);
#pragma unroll
            for (int bb2 = 0; bb2 < 2; bb2++) {
                uint32_t r0, r1, r2, r3;
                ldmat4(r0, r1, r2, r3,
                       sB + (wn * 32 + bb2 * 16 + lmrow) * GROWB + (kb * 2 + lmunit) * 16);
#pragma unroll
                for (int am = 0; am < 4; am++) {
                    mma16816h(acc[am][bb2 * 2],     a[am][0], a[am][1], a[am][2], a[am][3], r0, r2);
                    mma16816h(acc[am][bb2 * 2 + 1], a[am][0], a[am][1], a[am][2], a[am][3], r1, r3);
                }
            }
        }
    }

    const int g = lane >> 2, it = lane & 3;
#pragma unroll
    for (int am = 0; am < 4; am++) {
        const int row0 = m0 + wm * 64 + am * 16 + g;
#pragma unroll
        for (int bn = 0; bn < 4; bn++) {
            const int col = n0 + wn * 32 + bn * 8 + it * 2;
            float* p0 = OUT + (size_t)row0 * 1024 + col;
            float* p1 = p0 + 8 * 1024;
            *(float2*)p0 = make_float2(acc[am][bn][0], acc[am][bn][1]);
            *(float2*)p1 = make_float2(acc[am][bn][2], acc[am][bn][3]);
        }
    }
}

// ================= HMMA flash attention (unchanged from R14) =========
#define TROW 272
#define QSZ (128 * TROW)                 // 34816
#define KVSUB (64 * TROW)                // 17408
#define VROW 144
#define VSUB (64 * VROW)                 // 9216
#define KVSTRIDE (KVSUB + VSUB)          // 26624
#define ATTN_SMEM (QSZ + 2 * KVSTRIDE)   // 88064

__global__ __launch_bounds__(256, 2)
void attn_tc(const float* __restrict__ mask,
             const __nv_bfloat16* __restrict__ Q2,
             const __nv_bfloat16* __restrict__ K2,
             const __half* __restrict__ Vh,
             __half* __restrict__ Aout) {
    extern __shared__ __align__(128) char smc[];
    const uint32_t sq = smem_u32(smc);

    const int tid = threadIdx.x;
    const int wid = tid >> 5;
    const int lane = tid & 31;
    const int g = lane >> 2, it = lane & 3;
    const int lmrow = ((lane >> 3) & 1) * 8 + (lane & 7);
    const int lmunit = lane >> 4;

    const int b = blockIdx.z, h = blockIdx.y;
    const int q0 = blockIdx.x * 128;
    const size_t brow = (size_t)b * SS;

#pragma unroll
    for (int i = 0; i < 8; i++) {
        int idx = tid + i * 256;
        int u = idx & 15, r = idx >> 4;
        cp16(sq + r * TROW + u * 16, Q2 + (brow + q0 + r) * 2048 + h * 128 + u * 8);
    }
    cp_commit();

#pragma unroll
    for (int i = 0; i < 4; i++) {
        int idx = tid + i * 256;
        int u = idx & 15, r = idx >> 4;
        cp16(sq + QSZ + r * TROW + u * 16, K2 + (brow + r) * 2048 + h * 128 + u * 8);
    }
#pragma unroll
    for (int i = 0; i < 2; i++) {
        int idx = tid + i * 256;
        int u = idx & 7, r = idx >> 3;
        cp16(sq + QSZ + KVSUB + r * VROW + u * 16, Vh + (brow + r) * 1024 + h * 64 + u * 8);
    }
    cp_commit();

    float o[8][4];
#pragma unroll
    for (int dn = 0; dn < 8; dn++)
#pragma unroll
        for (int j = 0; j < 4; j++) o[dn][j] = 0.f;
    float mst0 = -INFINITY, mst1 = -INFINITY, l0 = 0.f, l1 = 0.f;

    const float* mrow0 = mask + ((size_t)b * SS + q0 + wid * 16 + g) * SS;
    const float* mrow1 = mrow0 + 8 * SS;

    uint32_t qh[4][4];
    bool qh_loaded = false;

    for (int st = 0; st < 32; st++) {
        const int cur = st & 1;
        cp_wait<0>();
        __syncthreads();

        if (st + 1 < 32) {
            const uint32_t kb = sq + QSZ + (uint32_t)(cur ^ 1) * KVSTRIDE;
            const size_t gbase = brow + (size_t)(st + 1) * 64;
#pragma unroll
            for (int i = 0; i < 4; i++) {
                int idx = tid + i * 256;
                int u = idx & 15, r = idx >> 4;
                cp16(kb + r * TROW + u * 16, K2 + (gbase + r) * 2048 + h * 128 + u * 8);
            }
#pragma unroll
            for (int i = 0; i < 2; i++) {
                int idx = tid + i * 256;
                int u = idx & 7, r = idx >> 3;
                cp16(kb + KVSUB + r * VROW + u * 16, Vh + (gbase + r) * 1024 + h * 64 + u * 8);
            }
            cp_commit();
        }

        if (!qh_loaded) {
            qh_loaded = true;
#pragma unroll
            for (int u4 = 0; u4 < 4; u4++)
                ldmat4(qh[u4][0], qh[u4][1], qh[u4][2], qh[u4][3],
                       sq + (wid * 16 + lmrow) * TROW + (u4 * 2 + lmunit) * 16);
        }

        const uint32_t sk = sq + QSZ + (uint32_t)cur * KVSTRIDE;
        const uint32_t sv = sk + KVSUB;

        float s[8][4];
#pragma unroll
        for (int nb = 0; nb < 8; nb++)
#pragma unroll
            for (int j = 0; j < 4; j++) s[nb][j] = 0.f;

#pragma unroll
        for (int u4 = 0; u4 < 4; u4++) {
            uint32_t ql0, ql1, ql2, ql3;
            ldmat4(ql0, ql1, ql2, ql3,
                   sq + (wid * 16 + lmrow) * TROW + (8 + u4 * 2 + lmunit) * 16);
#pragma unroll
            for (int nb16 = 0; nb16 < 4; nb16++) {
                uint32_t r0, r1, r2, r3;
                ldmat4(r0, r1, r2, r3,
                       sk + (nb16 * 16 + lmrow) * TROW + (u4 * 2 + lmunit) * 16);
                mma16816(s[nb16 * 2],     qh[u4][0], qh[u4][1], qh[u4][2], qh[u4][3], r0, r2);
                mma16816(s[nb16 * 2 + 1], qh[u4][0], qh[u4][1], qh[u4][2], qh[u4][3], r1, r3);
                mma16816(s[nb16 * 2],     ql0, ql1, ql2, ql3, r0, r2);
                mma16816(s[nb16 * 2 + 1], ql0, ql1, ql2, ql3, r1, r3);
            }
#pragma unroll
            for (int nb16 = 0; nb16 < 4; nb16++) {
                uint32_t r0, r1, r2, r3;
                ldmat4(r0, r1, r2, r3,
                       sk + (nb16 * 16 + lmrow) * TROW + (8 + u4 * 2 + lmunit) * 16);
                mma16816(s[nb16 * 2],     qh[u4][0], qh[u4][1], qh[u4][2], qh[u4][3], r0, r2);
                mma16816(s[nb16 * 2 + 1], qh[u4][0], qh[u4][1], qh[u4][2], qh[u4][3], r1, r3);
            }
        }

        float mx0 = -INFINITY, mx1 = -INFINITY;
#pragma unroll
        for (int nb = 0; nb < 8; nb++) {
            const int col = st * 64 + nb * 8 + it * 2;
            float2 m0 = *(const float2*)(mrow0 + col);
            float2 m1 = *(const float2*)(mrow1 + col);
            s[nb][0] = fmaf(s[nb][0], 0.125f, m0.x);
            s[nb][1] = fmaf(s[nb][1], 0.125f, m0.y);
            s[nb][2] = fmaf(s[nb][2], 0.125f, m1.x);
            s[nb][3] = fmaf(s[nb][3], 0.125f, m1.y);
            mx0 = fmaxf(mx0, fmaxf(s[nb][0], s[nb][1]));
            mx1 = fmaxf(mx1, fmaxf(s[nb][2], s[nb][3]));
        }
        mx0 = fmaxf(mx0, __shfl_xor_sync(0xffffffffu, mx0, 1));
        mx0 = fmaxf(mx0, __shfl_xor_sync(0xffffffffu, mx0, 2));
        mx1 = fmaxf(mx1, __shfl_xor_sync(0xffffffffu, mx1, 1));
        mx1 = fmaxf(mx1, __shfl_xor_sync(0xffffffffu, mx1, 2));

        const float nm0 = fmaxf(mst0, mx0), nm1 = fmaxf(mst1, mx1);
        const float corr0 = __expf(mst0 - nm0), corr1 = __expf(mst1 - nm1);
        mst0 = nm0; mst1 = nm1;

        uint32_t ph[16];
        float sum0 = 0.f, sum1 = 0.f;
#pragma unroll
        for (int nb = 0; nb < 8; nb++) {
            float p0 = __expf(s[nb][0] - nm0);
            float p1 = __expf(s[nb][1] - nm0);
            float p2 = __expf(s[nb][2] - nm1);
            float p3 = __expf(s[nb][3] - nm1);
            sum0 += p0 + p1; sum1 += p2 + p3;
            const int u = nb >> 1;
            const int base = u * 4 + (nb & 1) * 2;
            ph[base]     = pack_h2(p0, p1);
            ph[base + 1] = pack_h2(p2, p3);
        }
        sum0 += __shfl_xor_sync(0xffffffffu, sum0, 1);
        sum0 += __shfl_xor_sync(0xffffffffu, sum0, 2);
        sum1 += __shfl_xor_sync(0xffffffffu, sum1, 1);
        sum1 += __shfl_xor_sync(0xffffffffu, sum1, 2);
        l0 = l0 * corr0 + sum0;
        l1 = l1 * corr1 + sum1;
#pragma unroll
        for (int dn = 0; dn < 8; dn++) {
            o[dn][0] *= corr0; o[dn][1] *= corr0;
            o[dn][2] *= corr1; o[dn][3] *= corr1;
        }

#pragma unroll
        for (int u = 0; u < 4; u++) {
            const uint32_t* ap = ph + u * 4;
#pragma unroll
            for (int dn16 = 0; dn16 < 4; dn16++) {
                uint32_t r0, r1, r2, r3;
                ldmat4t(r0, r1, r2, r3,
                        sv + (u * 16 + lmrow) * VROW + (dn16 * 2 + lmunit) * 16);
                mma16816h(o[dn16 * 2],     ap[0], ap[1], ap[2], ap[3], r0, r1);
                mma16816h(o[dn16 * 2 + 1], ap[0], ap[1], ap[2], ap[3], r2, r3);
            }
        }
    }

    const float inv0 = 1.f / l0, inv1 = 1.f / l1;
    const size_t row0 = brow + q0 + wid * 16 + g;
#pragma unroll
    for (int dn = 0; dn < 8; dn++) {
        const int col = h * 64 + dn * 8 + it * 2;
        __half2 a01 = __floats2half2_rn(o[dn][0] * inv0, o[dn][1] * inv0);
        __half2 a23 = __floats2half2_rn(o[dn][2] * inv1, o[dn][3] * inv1);
        *(__half2*)(Aout + row0 * 1024 + col) = a01;
        *(__half2*)(Aout + (row0 + 8) * 1024 + col) = a23;
    }
}

// ---------------- launch ----------------
extern "C" void kernel_launch(void* const* d_in, const int* in_sizes, int n_in,
                              void* d_out, int out_size) {
    (void)in_sizes; (void)n_in; (void)out_size;
    const float* hidden = (const float*)d_in[0];
    const float* mask   = (const float*)d_in[1];
    const float* qs = (const float*)d_in[2];
    const float* qd = (const float*)d_in[3];
    const float* ks = (const float*)d_in[4];
    const float* kd = (const float*)d_in[5];
    const float* vs = (const float*)d_in[6];
    const float* vd = (const float*)d_in[7];
    const float* os = (const float*)d_in[8];
    const float* od = (const float*)d_in[9];

    __nv_bfloat16 *a2, *wq2, *wk2, *q2, *k2;
    __half *ah, *wvh, *woh, *vh;
    cudaGetSymbolAddress((void**)&a2,  g_a2);
    cudaGetSymbolAddress((void**)&ah,  g_ah);
    cudaGetSymbolAddress((void**)&wq2, g_wq2);
    cudaGetSymbolAddress((void**)&wk2, g_wk2);
    cudaGetSymbolAddress((void**)&wvh, g_wvh);
    cudaGetSymbolAddress((void**)&woh, g_woh);
    cudaGetSymbolAddress((void**)&q2,  g_q2);
    cudaGetSymbolAddress((void**)&k2,  g_k2);
    cudaGetSymbolAddress((void**)&vh,  g_vh);

    cudaFuncSetAttribute(tc_proj, cudaFuncAttributeMaxDynamicSharedMemorySize, GSMEM4);
    cudaFuncSetAttribute(tc_gemm_o, cudaFuncAttributeMaxDynamicSharedMemorySize, GSMEM4);
    cudaFuncSetAttribute(attn_tc, cudaFuncAttributeMaxDynamicSharedMemorySize, ATTN_SMEM);

    // fused prep
    prep_kernel<<<dim3(1024, 5), 256>>>(hidden, qs, qd, ks, kd, vs, vd, os, od,
                                        a2, ah, wq2, wk2, wvh, woh);

    // Q,K,V projections in ONE launch (z=0,1 bf16 QK; z=2 fp16 V)
    tc_proj<<<dim3(8, 16, 3), 512, GSMEM4>>>(a2, wq2, wk2, ah, wvh, q2, k2, vh);

    // attention -> fp16 single output into g_ah (reused)
    attn_tc<<<dim3(SS / 128, NHH, BB), 256, ATTN_SMEM>>>(mask, q2, k2, vh, ah);

    // O projection (fp16 2-term) -> fp32 d_out
    tc_gemm_o<<<dim3(8, 16, 1), 512, GSMEM4>>>(ah, woh, (float*)d_out);
}

// round 16
// speedup vs baseline: 1.0050x; 1.0050x over previous
#include <cuda_runtime.h>
#include <cuda_bf16.h>
#include <cuda_fp16.h>
#include <cstdint>

// Problem dims
#define BB  2
#define SS  2048
#define HH  1024
#define NHH 16
#define HDD 64
#define MM  (BB*SS)          // 4096 rows

// ---------------- scratch (no cudaMalloc allowed) ----------------
__device__ __nv_bfloat16 g_a2[MM * 2048];        // bf16 hi|lo split activations
__device__ __half        g_ah[MM * 1024];        // fp16 single activations / attn out
__device__ __nv_bfloat16 g_wq2[HH * 2048];
__device__ __nv_bfloat16 g_wk2[HH * 2048];
__device__ __half        g_wvh[HH * 2048];       // fp16 split
__device__ __half        g_woh[HH * 2048];
__device__ __nv_bfloat16 g_q2[MM * 2048];        // per-head split [row][h*128+(hi|lo)]
__device__ __nv_bfloat16 g_k2[MM * 2048];
__device__ __half g_vh[MM * 1024];               // fp16 single per-head [row][h*64+d]

// ================= PTX helpers =================
__device__ __forceinline__ uint32_t smem_u32(const void* p) {
    uint32_t a;
    asm("{ .reg .u64 t; cvta.to.shared.u64 t, %1; cvt.u32.u64 %0, t; }" : "=r"(a) : "l"(p));
    return a;
}
__device__ __forceinline__ void cp16(uint32_t dst, const void* src) {
    asm volatile("cp.async.cg.shared.global [%0], [%1], 16;" :: "r"(dst), "l"(src));
}
__device__ __forceinline__ void cp_commit() {
    asm volatile("cp.async.commit_group;" ::: "memory");
}
template<int N> __device__ __forceinline__ void cp_wait() {
    asm volatile("cp.async.wait_group %0;" :: "n"(N) : "memory");
}
__device__ __forceinline__ void ldmat4(uint32_t& r0, uint32_t& r1, uint32_t& r2, uint32_t& r3,
                                       uint32_t addr) {
    asm volatile("ldmatrix.sync.aligned.m8n8.x4.shared.b16 {%0,%1,%2,%3}, [%4];"
                 : "=r"(r0), "=r"(r1), "=r"(r2), "=r"(r3) : "r"(addr));
}
__device__ __forceinline__ void ldmat4t(uint32_t& r0, uint32_t& r1, uint32_t& r2, uint32_t& r3,
                                        uint32_t addr) {
    asm volatile("ldmatrix.sync.aligned.m8n8.x4.trans.shared.b16 {%0,%1,%2,%3}, [%4];"
                 : "=r"(r0), "=r"(r1), "=r"(r2), "=r"(r3) : "r"(addr));
}
__device__ __forceinline__ void mma16816(float* d, uint32_t a0, uint32_t a1, uint32_t a2,
                                         uint32_t a3, uint32_t b0, uint32_t b1) {
    asm volatile("mma.sync.aligned.m16n8k16.row.col.f32.bf16.bf16.f32 "
                 "{%0,%1,%2,%3},{%4,%5,%6,%7},{%8,%9},{%0,%1,%2,%3};"
                 : "+f"(d[0]), "+f"(d[1]), "+f"(d[2]), "+f"(d[3])
                 : "r"(a0), "r"(a1), "r"(a2), "r"(a3), "r"(b0), "r"(b1));
}
__device__ __forceinline__ void mma16816h(float* d, uint32_t a0, uint32_t a1, uint32_t a2,
                                          uint32_t a3, uint32_t b0, uint32_t b1) {
    asm volatile("mma.sync.aligned.m16n8k16.row.col.f32.f16.f16.f32 "
                 "{%0,%1,%2,%3},{%4,%5,%6,%7},{%8,%9},{%0,%1,%2,%3};"
                 : "+f"(d[0]), "+f"(d[1]), "+f"(d[2]), "+f"(d[3])
                 : "r"(a0), "r"(a1), "r"(a2), "r"(a3), "r"(b0), "r"(b1));
}
__device__ __forceinline__ uint32_t pack_h2(float x, float y) {
    __half2 t = __floats2half2_rn(x, y);
    return *(uint32_t*)&t;
}

// ================= fused prep =================
__device__ __forceinline__ void split_bf(const float* __restrict__ a,
                                         const float* __restrict__ b,
                                         __nv_bfloat16* __restrict__ out, int i) {
    int r = i >> 8;
    int c4 = (i & 255) << 2;
    float4 x = ((const float4*)a)[i];
    if (b) {
        float4 y = ((const float4*)b)[i];
        x.x += y.x; x.y += y.y; x.z += y.z; x.w += y.w;
    }
    float vf[4] = {x.x, x.y, x.z, x.w};
    __nv_bfloat16 h[4], l[4];
#pragma unroll
    for (int j = 0; j < 4; j++) {
        h[j] = __float2bfloat16_rn(vf[j]);
        l[j] = __float2bfloat16_rn(vf[j] - __bfloat162float(h[j]));
    }
    __nv_bfloat16* o = out + (size_t)r * 2048 + c4;
    ((__nv_bfloat162*)o)[0] = __halves2bfloat162(h[0], h[1]);
    ((__nv_bfloat162*)o)[1] = __halves2bfloat162(h[2], h[3]);
    ((__nv_bfloat162*)(o + 1024))[0] = __halves2bfloat162(l[0], l[1]);
    ((__nv_bfloat162*)(o + 1024))[1] = __halves2bfloat162(l[2], l[3]);
}

__device__ __forceinline__ void split_h(const float* __restrict__ a,
                                        const float* __restrict__ b,
                                        __half* __restrict__ out, int i) {
    int r = i >> 8;
    int c4 = (i & 255) << 2;
    float4 x = ((const float4*)a)[i];
    float4 y = ((const float4*)b)[i];
    x.x += y.x; x.y += y.y; x.z += y.z; x.w += y.w;
    float vf[4] = {x.x, x.y, x.z, x.w};
    __half h[4], l[4];
#pragma unroll
    for (int j = 0; j < 4; j++) {
        h[j] = __float2half_rn(vf[j]);
        l[j] = __float2half_rn(vf[j] - __half2float(h[j]));
    }
    __half* o = out + (size_t)r * 2048 + c4;
    ((__half2*)o)[0] = __halves2half2(h[0], h[1]);
    ((__half2*)o)[1] = __halves2half2(h[2], h[3]);
    ((__half2*)(o + 1024))[0] = __halves2half2(l[0], l[1]);
    ((__half2*)(o + 1024))[1] = __halves2half2(l[2], l[3]);
}

__global__ void prep_kernel(const float* __restrict__ hid,
                            const float* __restrict__ s0, const float* __restrict__ d0,
                            const float* __restrict__ s1, const float* __restrict__ d1,
                            const float* __restrict__ s2, const float* __restrict__ d2,
                            const float* __restrict__ s3, const float* __restrict__ d3,
                            __nv_bfloat16* __restrict__ oa, __half* __restrict__ oah,
                            __nv_bfloat16* __restrict__ o0, __nv_bfloat16* __restrict__ o1,
                            __half* __restrict__ o2, __half* __restrict__ o3) {
    const int y = blockIdx.y;
    const int base = blockIdx.x * 256 + threadIdx.x;
    if (y == 4) {
#pragma unroll
        for (int k = 0; k < 4; k++) {
            const int i = base + k * 262144;
            split_bf(hid, nullptr, oa, i);
            float4 x = ((const float4*)hid)[i];
            int r = i >> 8, c4 = (i & 255) << 2;
            __half* o = oah + (size_t)r * 1024 + c4;
            ((__half2*)o)[0] = __floats2half2_rn(x.x, x.y);
            ((__half2*)o)[1] = __floats2half2_rn(x.z, x.w);
        }
    } else if (y == 0) split_bf(s0, d0, o0, base);
    else if (y == 1) split_bf(s1, d1, o1, base);
    else if (y == 2) split_h(s2, d2, o2, base);
    else             split_h(s3, d3, o3, base);
}

// ================= bf16 3-term GEMM (Q,K projections; 256x128 tiles, R14 config) ======
#define GROWB 144
#define GATILE (256 * GROWB)             // 36864
#define GBTILE (128 * GROWB)             // 18432
#define GSTAGEB (GATILE + GBTILE)        // 55296
#define GSMEM (3 * GSTAGEB)              // 165888
#define GNCH 48
#define HNCH 32

__global__ __launch_bounds__(512, 1)
void tc_gemm(const __nv_bfloat16* __restrict__ A2,
             const __nv_bfloat16* __restrict__ W2q,
             const __nv_bfloat16* __restrict__ W2k,
             __nv_bfloat16* __restrict__ O0, __nv_bfloat16* __restrict__ O1) {
    extern __shared__ __align__(128) char smbuf[];
    const uint32_t sbase = smem_u32(smbuf);

    const __nv_bfloat16* W2 = (blockIdx.z == 0) ? W2q : W2k;
    __nv_bfloat16* OUT = (blockIdx.z == 0) ? O0 : O1;

    const int tid = threadIdx.x;
    const int wid = tid >> 5;
    const int lane = tid & 31;
    const int m0 = blockIdx.y * 256;
    const int n0 = blockIdx.x * 128;

    const int tAr = tid >> 1, tAh = tid & 1;
    const int tBr = tid >> 2, tBq = tid & 3;
    const __nv_bfloat16* gA = A2 + (size_t)(m0 + tAr) * 2048 + tAh * 32;
    const __nv_bfloat16* gB = W2 + (size_t)(n0 + tBr) * 2048 + tBq * 16;
    const uint32_t sdA0 = sbase + tAr * GROWB + tAh * 64;
    const uint32_t sdB0 = sbase + GATILE + tBr * GROWB + tBq * 32;
    const int offA[3] = { 0, 0, 1024 };
    const int offB[3] = { 0, 1024, 0 };

    const int mi = lane >> 3, rr = lane & 7;
    const int lmrow = (mi & 1) * 8 + rr;
    const int lmunit = (mi >> 1);
    const int wm = wid >> 2;
    const int wn = wid & 3;

    float acc[4][4][4];
#pragma unroll
    for (int am = 0; am < 4; am++)
#pragma unroll
        for (int bn = 0; bn < 4; bn++)
#pragma unroll
            for (int j = 0; j < 4; j++) acc[am][bn][j] = 0.f;

#pragma unroll
    for (int p = 0; p < 2; p++) {
        const __nv_bfloat16* sAg = gA + offA[0] + p * 64;
        const __nv_bfloat16* sBg = gB + offB[0] + p * 64;
        const uint32_t dA = sdA0 + p * GSTAGEB;
        const uint32_t dB = sdB0 + p * GSTAGEB;
#pragma unroll
        for (int q = 0; q < 4; q++) cp16(dA + q * 16, sAg + q * 8);
#pragma unroll
        for (int q = 0; q < 2; q++) cp16(dB + q * 16, sBg + q * 8);
        cp_commit();
    }

    for (int c = 0; c < GNCH; ++c) {
        if (c + 1 < GNCH) cp_wait<1>(); else cp_wait<0>();
        __syncthreads();

        if (c + 2 < GNCH) {
            const int cn = c + 2;
            const int t = cn >> 4, kc = cn & 15;
            const __nv_bfloat16* sAg = gA + offA[t] + kc * 64;
            const __nv_bfloat16* sBg = gB + offB[t] + kc * 64;
            const uint32_t dA = sdA0 + (uint32_t)(cn % 3) * GSTAGEB;
            const uint32_t dB = sdB0 + (uint32_t)(cn % 3) * GSTAGEB;
#pragma unroll
            for (int q = 0; q < 4; q++) cp16(dA + q * 16, sAg + q * 8);
#pragma unroll
            for (int q = 0; q < 2; q++) cp16(dB + q * 16, sBg + q * 8);
            cp_commit();
        }

        const uint32_t sA = sbase + (uint32_t)(c % 3) * GSTAGEB;
        const uint32_t sB = sA + GATILE;
#pragma unroll
        for (int kb = 0; kb < 4; kb++) {
            uint32_t a[4][4];
#pragma unroll
            for (int am = 0; am < 4; am++)
                ldmat4(a[am][0], a[am][1], a[am][2], a[am][3],
                       sA + (wm * 64 + am * 16 + lmrow) * GROWB + (kb * 2 + lmunit) * 16);
#pragma unroll
            for (int bb2 = 0; bb2 < 2; bb2++) {
                uint32_t r0, r1, r2, r3;
                ldmat4(r0, r1, r2, r3,
                       sB + (wn * 32 + bb2 * 16 + lmrow) * GROWB + (kb * 2 + lmunit) * 16);
#pragma unroll
                for (int am = 0; am < 4; am++) {
                    mma16816(acc[am][bb2 * 2],     a[am][0], a[am][1], a[am][2], a[am][3], r0, r2);
                    mma16816(acc[am][bb2 * 2 + 1], a[am][0], a[am][1], a[am][2], a[am][3], r1, r3);
                }
            }
        }
    }

    const int g = lane >> 2, it = lane & 3;
#pragma unroll
    for (int am = 0; am < 4; am++) {
        const int row0 = m0 + wm * 64 + am * 16 + g;
#pragma unroll
        for (int bn = 0; bn < 4; bn++) {
            const int col = n0 + wn * 32 + bn * 8 + it * 2;
            const int h = col >> 6, d = col & 63;
#pragma unroll
            for (int half_i = 0; half_i < 2; half_i++) {
                float v0 = acc[am][bn][half_i * 2], v1 = acc[am][bn][half_i * 2 + 1];
                __nv_bfloat16 h0 = __float2bfloat16_rn(v0);
                __nv_bfloat16 h1 = __float2bfloat16_rn(v1);
                __nv_bfloat162 hi2; hi2.x = h0; hi2.y = h1;
                __nv_bfloat162 lo2;
                lo2.x = __float2bfloat16_rn(v0 - __bfloat162float(h0));
                lo2.y = __float2bfloat16_rn(v1 - __bfloat162float(h1));
                __nv_bfloat16* op = OUT + (size_t)(row0 + half_i * 8) * 2048 + h * 128 + d;
                *(__nv_bfloat162*)op = hi2;
                *(__nv_bfloat162*)(op + 64) = lo2;
            }
        }
    }
}

// ================= fp16 2-term GEMM (V and O projections; R14 config) ========
template<int EP>
__global__ __launch_bounds__(512, 1)
void tc_gemm_h(const __half* __restrict__ Ah,
               const __half* __restrict__ Wh,
               void* __restrict__ OUT) {
    extern __shared__ __align__(128) char smbuf[];
    const uint32_t sbase = smem_u32(smbuf);

    const int tid = threadIdx.x;
    const int wid = tid >> 5;
    const int lane = tid & 31;
    const int m0 = blockIdx.y * 256;
    const int n0 = blockIdx.x * 128;

    const int tAr = tid >> 1, tAh = tid & 1;
    const int tBr = tid >> 2, tBq = tid & 3;
    const __half* gA = Ah + (size_t)(m0 + tAr) * 1024 + tAh * 32;
    const __half* gB = Wh + (size_t)(n0 + tBr) * 2048 + tBq * 16;
    const uint32_t sdA0 = sbase + tAr * GROWB + tAh * 64;
    const uint32_t sdB0 = sbase + GATILE + tBr * GROWB + tBq * 32;

    const int mi = lane >> 3, rr = lane & 7;
    const int lmrow = (mi & 1) * 8 + rr;
    const int lmunit = (mi >> 1);
    const int wm = wid >> 2;
    const int wn = wid & 3;

    float acc[4][4][4];
#pragma unroll
    for (int am = 0; am < 4; am++)
#pragma unroll
        for (int bn = 0; bn < 4; bn++)
#pragma unroll
            for (int j = 0; j < 4; j++) acc[am][bn][j] = 0.f;

#pragma unroll
    for (int p = 0; p < 2; p++) {
        const __half* sAg = gA + p * 64;
        const __half* sBg = gB + p * 64;
        const uint32_t dA = sdA0 + p * GSTAGEB;
        const uint32_t dB = sdB0 + p * GSTAGEB;
#pragma unroll
        for (int q = 0; q < 4; q++) cp16(dA + q * 16, sAg + q * 8);
#pragma unroll
        for (int q = 0; q < 2; q++) cp16(dB + q * 16, sBg + q * 8);
        cp_commit();
    }

    for (int c = 0; c < HNCH; ++c) {
        if (c + 1 < HNCH) cp_wait<1>(); else cp_wait<0>();
        __syncthreads();

        if (c + 2 < HNCH) {
            const int cn = c + 2;
            const int t = cn >> 4, kc = cn & 15;
            const __half* sAg = gA + kc * 64;
            const __half* sBg = gB + t * 1024 + kc * 64;
            const uint32_t dA = sdA0 + (uint32_t)(cn % 3) * GSTAGEB;
            const uint32_t dB = sdB0 + (uint32_t)(cn % 3) * GSTAGEB;
#pragma unroll
            for (int q = 0; q < 4; q++) cp16(dA + q * 16, sAg + q * 8);
#pragma unroll
            for (int q = 0; q < 2; q++) cp16(dB + q * 16, sBg + q * 8);
            cp_commit();
        }

        const uint32_t sA = sbase + (uint32_t)(c % 3) * GSTAGEB;
        const uint32_t sB = sA + GATILE;
#pragma unroll
        for (int kb = 0; kb < 4; kb++) {
            uint32_t a[4][4];
#pragma unroll
            for (int am = 0; am < 4; am++)
                ldmat4(a[am][0], a[am][1], a[am][2], a[am][3],
                       sA + (wm * 64 + am * 16 + lmrow) * GROWB + (kb * 2 + lmunit) * 16);
#pragma unroll
            for (int bb2 = 0; bb2 < 2; bb2++) {
                uint32_t r0, r1, r2, r3;
                ldmat4(r0, r1, r2, r3,
                       sB + (wn * 32 + bb2 * 16 + lmrow) * GROWB + (kb * 2 + lmunit) * 16);
#pragma unroll
                for (int am = 0; am < 4; am++) {
                    mma16816h(acc[am][bb2 * 2],     a[am][0], a[am][1], a[am][2], a[am][3], r0, r2);
                    mma16816h(acc[am][bb2 * 2 + 1], a[am][0], a[am][1], a[am][2], a[am][3], r1, r3);
                }
            }
        }
    }

    const int g = lane >> 2, it = lane & 3;
#pragma unroll
    for (int am = 0; am < 4; am++) {
        const int row0 = m0 + wm * 64 + am * 16 + g;
#pragma unroll
        for (int bn = 0; bn < 4; bn++) {
            const int col = n0 + wn * 32 + bn * 8 + it * 2;
            if (EP == 0) {
                float* p0 = (float*)OUT + (size_t)row0 * 1024 + col;
                float* p1 = p0 + 8 * 1024;
                *(float2*)p0 = make_float2(acc[am][bn][0], acc[am][bn][1]);
                *(float2*)p1 = make_float2(acc[am][bn][2], acc[am][bn][3]);
            } else {
                const int h = col >> 6, d = col & 63;
#pragma unroll
                for (int half_i = 0; half_i < 2; half_i++) {
                    __half2 hv = __floats2half2_rn(acc[am][bn][half_i * 2],
                                                   acc[am][bn][half_i * 2 + 1]);
                    __half* op = (__half*)OUT
                        + (size_t)(row0 + half_i * 8) * 1024 + h * 64 + d;
                    *(__half2*)op = hv;
                }
            }
        }
    }
}

// ================= HMMA flash attention: triple-buffered K/V, wait<1> =========
#define TROW 272
#define QSZ (128 * TROW)                 // 34816
#define KVSUB (64 * TROW)                // 17408
#define VROW 144
#define VSUB (64 * VROW)                 // 9216
#define KVSTRIDE (KVSUB + VSUB)          // 26624
#define ATTN_SMEM (QSZ + 3 * KVSTRIDE)   // 114688

__global__ __launch_bounds__(256, 2)
void attn_tc(const float* __restrict__ mask,
             const __nv_bfloat16* __restrict__ Q2,
             const __nv_bfloat16* __restrict__ K2,
             const __half* __restrict__ Vh,
             __half* __restrict__ Aout) {
    extern __shared__ __align__(128) char smc[];
    const uint32_t sq = smem_u32(smc);

    const int tid = threadIdx.x;
    const int wid = tid >> 5;
    const int lane = tid & 31;
    const int g = lane >> 2, it = lane & 3;
    const int lmrow = ((lane >> 3) & 1) * 8 + (lane & 7);
    const int lmunit = lane >> 4;

    const int b = blockIdx.z, h = blockIdx.y;
    const int q0 = blockIdx.x * 128;
    const size_t brow = (size_t)b * SS;

    // Q tile (group 0)
#pragma unroll
    for (int i = 0; i < 8; i++) {
        int idx = tid + i * 256;
        int u = idx & 15, r = idx >> 4;
        cp16(sq + r * TROW + u * 16, Q2 + (brow + q0 + r) * 2048 + h * 128 + u * 8);
    }
    cp_commit();

    // subtiles 0,1 -> buffers 0,1
#pragma unroll
    for (int p = 0; p < 2; p++) {
        const uint32_t kb = sq + QSZ + (uint32_t)p * KVSTRIDE;
        const size_t gbase = brow + (size_t)p * 64;
#pragma unroll
        for (int i = 0; i < 4; i++) {
            int idx = tid + i * 256;
            int u = idx & 15, r = idx >> 4;
            cp16(kb + r * TROW + u * 16, K2 + (gbase + r) * 2048 + h * 128 + u * 8);
        }
#pragma unroll
        for (int i = 0; i < 2; i++) {
            int idx = tid + i * 256;
            int u = idx & 7, r = idx >> 3;
            cp16(kb + KVSUB + r * VROW + u * 16, Vh + (gbase + r) * 1024 + h * 64 + u * 8);
        }
        cp_commit();
    }

    float o[8][4];
#pragma unroll
    for (int dn = 0; dn < 8; dn++)
#pragma unroll
        for (int j = 0; j < 4; j++) o[dn][j] = 0.f;
    float mst0 = -INFINITY, mst1 = -INFINITY, l0 = 0.f, l1 = 0.f;

    const float* mrow0 = mask + ((size_t)b * SS + q0 + wid * 16 + g) * SS;
    const float* mrow1 = mrow0 + 8 * SS;

    uint32_t qh[4][4];
    bool qh_loaded = false;

    for (int st = 0; st < 32; st++) {
        const uint32_t buf = (uint32_t)(st % 3);
        if (st < 31) cp_wait<1>(); else cp_wait<0>();
        __syncthreads();

        if (st + 2 < 32) {
            const uint32_t kb = sq + QSZ + (uint32_t)((st + 2) % 3) * KVSTRIDE;
            const size_t gbase = brow + (size_t)(st + 2) * 64;
#pragma unroll
            for (int i = 0; i < 4; i++) {
                int idx = tid + i * 256;
                int u = idx & 15, r = idx >> 4;
                cp16(kb + r * TROW + u * 16, K2 + (gbase + r) * 2048 + h * 128 + u * 8);
            }
#pragma unroll
            for (int i = 0; i < 2; i++) {
                int idx = tid + i * 256;
                int u = idx & 7, r = idx >> 3;
                cp16(kb + KVSUB + r * VROW + u * 16, Vh + (gbase + r) * 1024 + h * 64 + u * 8);
            }
            cp_commit();
        }

        if (!qh_loaded) {
            qh_loaded = true;
#pragma unroll
            for (int u4 = 0; u4 < 4; u4++)
                ldmat4(qh[u4][0], qh[u4][1], qh[u4][2], qh[u4][3],
                       sq + (wid * 16 + lmrow) * TROW + (u4 * 2 + lmunit) * 16);
        }

        const uint32_t sk = sq + QSZ + buf * KVSTRIDE;
        const uint32_t sv = sk + KVSUB;

        // ---- S = 3-term QK^T (bf16 split) ----
        float s[8][4];
#pragma unroll
        for (int nb = 0; nb < 8; nb++)
#pragma unroll
            for (int j = 0; j < 4; j++) s[nb][j] = 0.f;

#pragma unroll
        for (int u4 = 0; u4 < 4; u4++) {
            uint32_t ql0, ql1, ql2, ql3;
            ldmat4(ql0, ql1, ql2, ql3,
                   sq + (wid * 16 + lmrow) * TROW + (8 + u4 * 2 + lmunit) * 16);
#pragma unroll
            for (int nb16 = 0; nb16 < 4; nb16++) {
                uint32_t r0, r1, r2, r3;
                ldmat4(r0, r1, r2, r3,
                       sk + (nb16 * 16 + lmrow) * TROW + (u4 * 2 + lmunit) * 16);
                mma16816(s[nb16 * 2],     qh[u4][0], qh[u4][1], qh[u4][2], qh[u4][3], r0, r2);
                mma16816(s[nb16 * 2 + 1], qh[u4][0], qh[u4][1], qh[u4][2], qh[u4][3], r1, r3);
                mma16816(s[nb16 * 2],     ql0, ql1, ql2, ql3, r0, r2);
                mma16816(s[nb16 * 2 + 1], ql0, ql1, ql2, ql3, r1, r3);
            }
#pragma unroll
            for (int nb16 = 0; nb16 < 4; nb16++) {
                uint32_t r0, r1, r2, r3;
                ldmat4(r0, r1, r2, r3,
                       sk + (nb16 * 16 + lmrow) * TROW + (8 + u4 * 2 + lmunit) * 16);
                mma16816(s[nb16 * 2],     qh[u4][0], qh[u4][1], qh[u4][2], qh[u4][3], r0, r2);
                mma16816(s[nb16 * 2 + 1], qh[u4][0], qh[u4][1], qh[u4][2], qh[u4][3], r1, r3);
            }
        }

        // ---- scale + mask + online softmax ----
        float mx0 = -INFINITY, mx1 = -INFINITY;
#pragma unroll
        for (int nb = 0; nb < 8; nb++) {
            const int col = st * 64 + nb * 8 + it * 2;
            float2 m0 = *(const float2*)(mrow0 + col);
            float2 m1 = *(const float2*)(mrow1 + col);
            s[nb][0] = fmaf(s[nb][0], 0.125f, m0.x);
            s[nb][1] = fmaf(s[nb][1], 0.125f, m0.y);
            s[nb][2] = fmaf(s[nb][2], 0.125f, m1.x);
            s[nb][3] = fmaf(s[nb][3], 0.125f, m1.y);
            mx0 = fmaxf(mx0, fmaxf(s[nb][0], s[nb][1]));
            mx1 = fmaxf(mx1, fmaxf(s[nb][2], s[nb][3]));
        }
        mx0 = fmaxf(mx0, __shfl_xor_sync(0xffffffffu, mx0, 1));
        mx0 = fmaxf(mx0, __shfl_xor_sync(0xffffffffu, mx0, 2));
        mx1 = fmaxf(mx1, __shfl_xor_sync(0xffffffffu, mx1, 1));
        mx1 = fmaxf(mx1, __shfl_xor_sync(0xffffffffu, mx1, 2));

        const float nm0 = fmaxf(mst0, mx0), nm1 = fmaxf(mst1, mx1);
        const float corr0 = __expf(mst0 - nm0), corr1 = __expf(mst1 - nm1);
        mst0 = nm0; mst1 = nm1;

        uint32_t ph[16];
        float sum0 = 0.f, sum1 = 0.f;
#pragma unroll
        for (int nb = 0; nb < 8; nb++) {
            float p0 = __expf(s[nb][0] - nm0);
            float p1 = __expf(s[nb][1] - nm0);
            float p2 = __expf(s[nb][2] - nm1);
            float p3 = __expf(s[nb][3] - nm1);
            sum0 += p0 + p1; sum1 += p2 + p3;
            const int u = nb >> 1;
            const int base = u * 4 + (nb & 1) * 2;
            ph[base]     = pack_h2(p0, p1);
            ph[base + 1] = pack_h2(p2, p3);
        }
        sum0 += __shfl_xor_sync(0xffffffffu, sum0, 1);
        sum0 += __shfl_xor_sync(0xffffffffu, sum0, 2);
        sum1 += __shfl_xor_sync(0xffffffffu, sum1, 1);
        sum1 += __shfl_xor_sync(0xffffffffu, sum1, 2);
        l0 = l0 * corr0 + sum0;
        l1 = l1 * corr1 + sum1;
#pragma unroll
        for (int dn = 0; dn < 8; dn++) {
            o[dn][0] *= corr0; o[dn][1] *= corr0;
            o[dn][2] *= corr1; o[dn][3] *= corr1;
        }

        // ---- O += P V, single-term fp16 ----
#pragma unroll
        for (int u = 0; u < 4; u++) {
            const uint32_t* ap = ph + u * 4;
#pragma unroll
            for (int dn16 = 0; dn16 < 4; dn16++) {
                uint32_t r0, r1, r2, r3;
                ldmat4t(r0, r1, r2, r3,
                        sv + (u * 16 + lmrow) * VROW + (dn16 * 2 + lmunit) * 16);
                mma16816h(o[dn16 * 2],     ap[0], ap[1], ap[2], ap[3], r0, r1);
                mma16816h(o[dn16 * 2 + 1], ap[0], ap[1], ap[2], ap[3], r2, r3);
            }
        }
    }

    // ---- epilogue: normalize, write fp16 single [row][1024] ----
    const float inv0 = 1.f / l0, inv1 = 1.f / l1;
    const size_t row0 = brow + q0 + wid * 16 + g;
#pragma unroll
    for (int dn = 0; dn < 8; dn++) {
        const int col = h * 64 + dn * 8 + it * 2;
        __half2 a01 = __floats2half2_rn(o[dn][0] * inv0, o[dn][1] * inv0);
        __half2 a23 = __floats2half2_rn(o[dn][2] * inv1, o[dn][3] * inv1);
        *(__half2*)(Aout + row0 * 1024 + col) = a01;
        *(__half2*)(Aout + (row0 + 8) * 1024 + col) = a23;
    }
}

// ---------------- launch ----------------
extern "C" void kernel_launch(void* const* d_in, const int* in_sizes, int n_in,
                              void* d_out, int out_size) {
    (void)in_sizes; (void)n_in; (void)out_size;
    const float* hidden = (const float*)d_in[0];
    const float* mask   = (const float*)d_in[1];
    const float* qs = (const float*)d_in[2];
    const float* qd = (const float*)d_in[3];
    const float* ks = (const float*)d_in[4];
    const float* kd = (const float*)d_in[5];
    const float* vs = (const float*)d_in[6];
    const float* vd = (const float*)d_in[7];
    const float* os = (const float*)d_in[8];
    const float* od = (const float*)d_in[9];

    __nv_bfloat16 *a2, *wq2, *wk2, *q2, *k2;
    __half *ah, *wvh, *woh, *vh;
    cudaGetSymbolAddress((void**)&a2,  g_a2);
    cudaGetSymbolAddress((void**)&ah,  g_ah);
    cudaGetSymbolAddress((void**)&wq2, g_wq2);
    cudaGetSymbolAddress((void**)&wk2, g_wk2);
    cudaGetSymbolAddress((void**)&wvh, g_wvh);
    cudaGetSymbolAddress((void**)&woh, g_woh);
    cudaGetSymbolAddress((void**)&q2,  g_q2);
    cudaGetSymbolAddress((void**)&k2,  g_k2);
    cudaGetSymbolAddress((void**)&vh,  g_vh);

    cudaFuncSetAttribute(tc_gemm, cudaFuncAttributeMaxDynamicSharedMemorySize, GSMEM);
    cudaFuncSetAttribute(tc_gemm_h<0>, cudaFuncAttributeMaxDynamicSharedMemorySize, GSMEM);
    cudaFuncSetAttribute(tc_gemm_h<1>, cudaFuncAttributeMaxDynamicSharedMemorySize, GSMEM);
    cudaFuncSetAttribute(attn_tc, cudaFuncAttributeMaxDynamicSharedMemorySize, ATTN_SMEM);

    // fused prep
    prep_kernel<<<dim3(1024, 5), 256>>>(hidden, qs, qd, ks, kd, vs, vd, os, od,
                                        a2, ah, wq2, wk2, wvh, woh);

    // Q,K projections (bf16 3-term)
    tc_gemm<<<dim3(8, 16, 2), 512, GSMEM>>>(a2, wq2, wk2, q2, k2);

    // V projection (fp16 2-term) -> per-head fp16
    tc_gemm_h<1><<<dim3(8, 16, 1), 512, GSMEM>>>(ah, wvh, vh);

    // attention -> fp16 single output into g_ah (reused)
    attn_tc<<<dim3(SS / 128, NHH, BB), 256, ATTN_SMEM>>>(mask, q2, k2, vh, ah);

    // O projection (fp16 2-term) -> fp32 d_out
    tc_gemm_h<0><<<dim3(8, 16, 1), 512, GSMEM>>>(ah, woh, (float*)d_out);
}

// round 17
// speedup vs baseline: 1.0086x; 1.0036x over previous
#include <cuda_runtime.h>
#include <cuda_bf16.h>
#include <cuda_fp16.h>
#include <cstdint>

// Problem dims
#define BB  2
#define SS  2048
#define HH  1024
#define NHH 16
#define HDD 64
#define MM  (BB*SS)          // 4096 rows

// ---------------- scratch (no cudaMalloc allowed) ----------------
__device__ __nv_bfloat16 g_a2[MM * 2048];        // bf16 hi|lo split activations
__device__ __half        g_ah[MM * 1024];        // fp16 single activations / attn out
__device__ __nv_bfloat16 g_wq2[HH * 2048];
__device__ __nv_bfloat16 g_wk2[HH * 2048];
__device__ __half        g_wvh[HH * 2048];       // fp16 split
__device__ __half        g_woh[HH * 2048];
__device__ __nv_bfloat16 g_q2[MM * 2048];        // per-head split [row][h*128+(hi|lo)]
__device__ __nv_bfloat16 g_k2[MM * 2048];
__device__ __half g_vh[MM * 1024];               // fp16 single per-head [row][h*64+d]

// ================= PTX helpers =================
__device__ __forceinline__ uint32_t smem_u32(const void* p) {
    uint32_t a;
    asm("{ .reg .u64 t; cvta.to.shared.u64 t, %1; cvt.u32.u64 %0, t; }" : "=r"(a) : "l"(p));
    return a;
}
__device__ __forceinline__ void cp16(uint32_t dst, const void* src) {
    asm volatile("cp.async.cg.shared.global [%0], [%1], 16;" :: "r"(dst), "l"(src));
}
__device__ __forceinline__ void cp_commit() {
    asm volatile("cp.async.commit_group;" ::: "memory");
}
template<int N> __device__ __forceinline__ void cp_wait() {
    asm volatile("cp.async.wait_group %0;" :: "n"(N) : "memory");
}
__device__ __forceinline__ void ldmat4(uint32_t& r0, uint32_t& r1, uint32_t& r2, uint32_t& r3,
                                       uint32_t addr) {
    asm volatile("ldmatrix.sync.aligned.m8n8.x4.shared.b16 {%0,%1,%2,%3}, [%4];"
                 : "=r"(r0), "=r"(r1), "=r"(r2), "=r"(r3) : "r"(addr));
}
__device__ __forceinline__ void ldmat4t(uint32_t& r0, uint32_t& r1, uint32_t& r2, uint32_t& r3,
                                        uint32_t addr) {
    asm volatile("ldmatrix.sync.aligned.m8n8.x4.trans.shared.b16 {%0,%1,%2,%3}, [%4];"
                 : "=r"(r0), "=r"(r1), "=r"(r2), "=r"(r3) : "r"(addr));
}
__device__ __forceinline__ void mma16816(float* d, uint32_t a0, uint32_t a1, uint32_t a2,
                                         uint32_t a3, uint32_t b0, uint32_t b1) {
    asm volatile("mma.sync.aligned.m16n8k16.row.col.f32.bf16.bf16.f32 "
                 "{%0,%1,%2,%3},{%4,%5,%6,%7},{%8,%9},{%0,%1,%2,%3};"
                 : "+f"(d[0]), "+f"(d[1]), "+f"(d[2]), "+f"(d[3])
                 : "r"(a0), "r"(a1), "r"(a2), "r"(a3), "r"(b0), "r"(b1));
}
__device__ __forceinline__ void mma16816h(float* d, uint32_t a0, uint32_t a1, uint32_t a2,
                                          uint32_t a3, uint32_t b0, uint32_t b1) {
    asm volatile("mma.sync.aligned.m16n8k16.row.col.f32.f16.f16.f32 "
                 "{%0,%1,%2,%3},{%4,%5,%6,%7},{%8,%9},{%0,%1,%2,%3};"
                 : "+f"(d[0]), "+f"(d[1]), "+f"(d[2]), "+f"(d[3])
                 : "r"(a0), "r"(a1), "r"(a2), "r"(a3), "r"(b0), "r"(b1));
}
__device__ __forceinline__ uint32_t pack_h2(float x, float y) {
    __half2 t = __floats2half2_rn(x, y);
    return *(uint32_t*)&t;
}

// ================= fused prep (balanced: grid (1024, 8)) =================
__device__ __forceinline__ void split_bf(const float* __restrict__ a,
                                         const float* __restrict__ b,
                                         __nv_bfloat16* __restrict__ out, int i) {
    int r = i >> 8;
    int c4 = (i & 255) << 2;
    float4 x = ((const float4*)a)[i];
    if (b) {
        float4 y = ((const float4*)b)[i];
        x.x += y.x; x.y += y.y; x.z += y.z; x.w += y.w;
    }
    float vf[4] = {x.x, x.y, x.z, x.w};
    __nv_bfloat16 h[4], l[4];
#pragma unroll
    for (int j = 0; j < 4; j++) {
        h[j] = __float2bfloat16_rn(vf[j]);
        l[j] = __float2bfloat16_rn(vf[j] - __bfloat162float(h[j]));
    }
    __nv_bfloat16* o = out + (size_t)r * 2048 + c4;
    ((__nv_bfloat162*)o)[0] = __halves2bfloat162(h[0], h[1]);
    ((__nv_bfloat162*)o)[1] = __halves2bfloat162(h[2], h[3]);
    ((__nv_bfloat162*)(o + 1024))[0] = __halves2bfloat162(l[0], l[1]);
    ((__nv_bfloat162*)(o + 1024))[1] = __halves2bfloat162(l[2], l[3]);
}

__device__ __forceinline__ void split_h(const float* __restrict__ a,
                                        const float* __restrict__ b,
                                        __half* __restrict__ out, int i) {
    int r = i >> 8;
    int c4 = (i & 255) << 2;
    float4 x = ((const float4*)a)[i];
    float4 y = ((const float4*)b)[i];
    x.x += y.x; x.y += y.y; x.z += y.z; x.w += y.w;
    float vf[4] = {x.x, x.y, x.z, x.w};
    __half h[4], l[4];
#pragma unroll
    for (int j = 0; j < 4; j++) {
        h[j] = __float2half_rn(vf[j]);
        l[j] = __float2half_rn(vf[j] - __half2float(h[j]));
    }
    __half* o = out + (size_t)r * 2048 + c4;
    ((__half2*)o)[0] = __halves2half2(h[0], h[1]);
    ((__half2*)o)[1] = __halves2half2(h[2], h[3]);
    ((__half2*)(o + 1024))[0] = __halves2half2(l[0], l[1]);
    ((__half2*)(o + 1024))[1] = __halves2half2(l[2], l[3]);
}

// grid (1024, 8): y=0 wq(bf16) y=1 wk(bf16) y=2 wv(fp16) y=3 wo(fp16)
//                 y=4..7 -> activation quarter (y-4): bf16 split + fp16 single
__global__ void prep_kernel(const float* __restrict__ hid,
                            const float* __restrict__ s0, const float* __restrict__ d0,
                            const float* __restrict__ s1, const float* __restrict__ d1,
                            const float* __restrict__ s2, const float* __restrict__ d2,
                            const float* __restrict__ s3, const float* __restrict__ d3,
                            __nv_bfloat16* __restrict__ oa, __half* __restrict__ oah,
                            __nv_bfloat16* __restrict__ o0, __nv_bfloat16* __restrict__ o1,
                            __half* __restrict__ o2, __half* __restrict__ o3) {
    const int y = blockIdx.y;
    const int base = blockIdx.x * 256 + threadIdx.x;
    if (y >= 4) {
        const int i = base + (y - 4) * 262144;
        split_bf(hid, nullptr, oa, i);
        float4 x = ((const float4*)hid)[i];
        int r = i >> 8, c4 = (i & 255) << 2;
        __half* o = oah + (size_t)r * 1024 + c4;
        ((__half2*)o)[0] = __floats2half2_rn(x.x, x.y);
        ((__half2*)o)[1] = __floats2half2_rn(x.z, x.w);
    } else if (y == 0) split_bf(s0, d0, o0, base);
    else if (y == 1) split_bf(s1, d1, o1, base);
    else if (y == 2) split_h(s2, d2, o2, base);
    else             split_h(s3, d3, o3, base);
}

// ================= bf16 3-term GEMM (Q,K projections; 256x128 tiles, R14 config) ======
#define GROWB 144
#define GATILE (256 * GROWB)             // 36864
#define GBTILE (128 * GROWB)             // 18432
#define GSTAGEB (GATILE + GBTILE)        // 55296
#define GSMEM (3 * GSTAGEB)              // 165888
#define GNCH 48
#define HNCH 32

__global__ __launch_bounds__(512, 1)
void tc_gemm(const __nv_bfloat16* __restrict__ A2,
             const __nv_bfloat16* __restrict__ W2q,
             const __nv_bfloat16* __restrict__ W2k,
             __nv_bfloat16* __restrict__ O0, __nv_bfloat16* __restrict__ O1) {
    extern __shared__ __align__(128) char smbuf[];
    const uint32_t sbase = smem_u32(smbuf);

    const __nv_bfloat16* W2 = (blockIdx.z == 0) ? W2q : W2k;
    __nv_bfloat16* OUT = (blockIdx.z == 0) ? O0 : O1;

    const int tid = threadIdx.x;
    const int wid = tid >> 5;
    const int lane = tid & 31;
    const int m0 = blockIdx.y * 256;
    const int n0 = blockIdx.x * 128;

    const int tAr = tid >> 1, tAh = tid & 1;
    const int tBr = tid >> 2, tBq = tid & 3;
    const __nv_bfloat16* gA = A2 + (size_t)(m0 + tAr) * 2048 + tAh * 32;
    const __nv_bfloat16* gB = W2 + (size_t)(n0 + tBr) * 2048 + tBq * 16;
    const uint32_t sdA0 = sbase + tAr * GROWB + tAh * 64;
    const uint32_t sdB0 = sbase + GATILE + tBr * GROWB + tBq * 32;
    const int offA[3] = { 0, 0, 1024 };
    const int offB[3] = { 0, 1024, 0 };

    const int mi = lane >> 3, rr = lane & 7;
    const int lmrow = (mi & 1) * 8 + rr;
    const int lmunit = (mi >> 1);
    const int wm = wid >> 2;
    const int wn = wid & 3;

    float acc[4][4][4];
#pragma unroll
    for (int am = 0; am < 4; am++)
#pragma unroll
        for (int bn = 0; bn < 4; bn++)
#pragma unroll
            for (int j = 0; j < 4; j++) acc[am][bn][j] = 0.f;

#pragma unroll
    for (int p = 0; p < 2; p++) {
        const __nv_bfloat16* sAg = gA + offA[0] + p * 64;
        const __nv_bfloat16* sBg = gB + offB[0] + p * 64;
        const uint32_t dA = sdA0 + p * GSTAGEB;
        const uint32_t dB = sdB0 + p * GSTAGEB;
#pragma unroll
        for (int q = 0; q < 4; q++) cp16(dA + q * 16, sAg + q * 8);
#pragma unroll
        for (int q = 0; q < 2; q++) cp16(dB + q * 16, sBg + q * 8);
        cp_commit();
    }

    for (int c = 0; c < GNCH; ++c) {
        if (c + 1 < GNCH) cp_wait<1>(); else cp_wait<0>();
        __syncthreads();

        if (c + 2 < GNCH) {
            const int cn = c + 2;
            const int t = cn >> 4, kc = cn & 15;
            const __nv_bfloat16* sAg = gA + offA[t] + kc * 64;
            const __nv_bfloat16* sBg = gB + offB[t] + kc * 64;
            const uint32_t dA = sdA0 + (uint32_t)(cn % 3) * GSTAGEB;
            const uint32_t dB = sdB0 + (uint32_t)(cn % 3) * GSTAGEB;
#pragma unroll
            for (int q = 0; q < 4; q++) cp16(dA + q * 16, sAg + q * 8);
#pragma unroll
            for (int q = 0; q < 2; q++) cp16(dB + q * 16, sBg + q * 8);
            cp_commit();
        }

        const uint32_t sA = sbase + (uint32_t)(c % 3) * GSTAGEB;
        const uint32_t sB = sA + GATILE;
#pragma unroll
        for (int kb = 0; kb < 4; kb++) {
            uint32_t a[4][4];
#pragma unroll
            for (int am = 0; am < 4; am++)
                ldmat4(a[am][0], a[am][1], a[am][2], a[am][3],
                       sA + (wm * 64 + am * 16 + lmrow) * GROWB + (kb * 2 + lmunit) * 16);
#pragma unroll
            for (int bb2 = 0; bb2 < 2; bb2++) {
                uint32_t r0, r1, r2, r3;
                ldmat4(r0, r1, r2, r3,
                       sB + (wn * 32 + bb2 * 16 + lmrow) * GROWB + (kb * 2 + lmunit) * 16);
#pragma unroll
                for (int am = 0; am < 4; am++) {
                    mma16816(acc[am][bb2 * 2],     a[am][0], a[am][1], a[am][2], a[am][3], r0, r2);
                    mma16816(acc[am][bb2 * 2 + 1], a[am][0], a[am][1], a[am][2], a[am][3], r1, r3);
                }
            }
        }
    }

    const int g = lane >> 2, it = lane & 3;
#pragma unroll
    for (int am = 0; am < 4; am++) {
        const int row0 = m0 + wm * 64 + am * 16 + g;
#pragma unroll
        for (int bn = 0; bn < 4; bn++) {
            const int col = n0 + wn * 32 + bn * 8 + it * 2;
            const int h = col >> 6, d = col & 63;
#pragma unroll
            for (int half_i = 0; half_i < 2; half_i++) {
                float v0 = acc[am][bn][half_i * 2], v1 = acc[am][bn][half_i * 2 + 1];
                __nv_bfloat16 h0 = __float2bfloat16_rn(v0);
                __nv_bfloat16 h1 = __float2bfloat16_rn(v1);
                __nv_bfloat162 hi2; hi2.x = h0; hi2.y = h1;
                __nv_bfloat162 lo2;
                lo2.x = __float2bfloat16_rn(v0 - __bfloat162float(h0));
                lo2.y = __float2bfloat16_rn(v1 - __bfloat162float(h1));
                __nv_bfloat16* op = OUT + (size_t)(row0 + half_i * 8) * 2048 + h * 128 + d;
                *(__nv_bfloat162*)op = hi2;
                *(__nv_bfloat162*)(op + 64) = lo2;
            }
        }
    }
}

// ================= fp16 2-term GEMM (V and O projections; R14 config) ========
template<int EP>
__global__ __launch_bounds__(512, 1)
void tc_gemm_h(const __half* __restrict__ Ah,
               const __half* __restrict__ Wh,
               void* __restrict__ OUT) {
    extern __shared__ __align__(128) char smbuf[];
    const uint32_t sbase = smem_u32(smbuf);

    const int tid = threadIdx.x;
    const int wid = tid >> 5;
    const int lane = tid & 31;
    const int m0 = blockIdx.y * 256;
    const int n0 = blockIdx.x * 128;

    const int tAr = tid >> 1, tAh = tid & 1;
    const int tBr = tid >> 2, tBq = tid & 3;
    const __half* gA = Ah + (size_t)(m0 + tAr) * 1024 + tAh * 32;
    const __half* gB = Wh + (size_t)(n0 + tBr) * 2048 + tBq * 16;
    const uint32_t sdA0 = sbase + tAr * GROWB + tAh * 64;
    const uint32_t sdB0 = sbase + GATILE + tBr * GROWB + tBq * 32;

    const int mi = lane >> 3, rr = lane & 7;
    const int lmrow = (mi & 1) * 8 + rr;
    const int lmunit = (mi >> 1);
    const int wm = wid >> 2;
    const int wn = wid & 3;

    float acc[4][4][4];
#pragma unroll
    for (int am = 0; am < 4; am++)
#pragma unroll
        for (int bn = 0; bn < 4; bn++)
#pragma unroll
            for (int j = 0; j < 4; j++) acc[am][bn][j] = 0.f;

#pragma unroll
    for (int p = 0; p < 2; p++) {
        const __half* sAg = gA + p * 64;
        const __half* sBg = gB + p * 64;
        const uint32_t dA = sdA0 + p * GSTAGEB;
        const uint32_t dB = sdB0 + p * GSTAGEB;
#pragma unroll
        for (int q = 0; q < 4; q++) cp16(dA + q * 16, sAg + q * 8);
#pragma unroll
        for (int q = 0; q < 2; q++) cp16(dB + q * 16, sBg + q * 8);
        cp_commit();
    }

    for (int c = 0; c < HNCH; ++c) {
        if (c + 1 < HNCH) cp_wait<1>(); else cp_wait<0>();
        __syncthreads();

        if (c + 2 < HNCH) {
            const int cn = c + 2;
            const int t = cn >> 4, kc = cn & 15;
            const __half* sAg = gA + kc * 64;
            const __half* sBg = gB + t * 1024 + kc * 64;
            const uint32_t dA = sdA0 + (uint32_t)(cn % 3) * GSTAGEB;
            const uint32_t dB = sdB0 + (uint32_t)(cn % 3) * GSTAGEB;
#pragma unroll
            for (int q = 0; q < 4; q++) cp16(dA + q * 16, sAg + q * 8);
#pragma unroll
            for (int q = 0; q < 2; q++) cp16(dB + q * 16, sBg + q * 8);
            cp_commit();
        }

        const uint32_t sA = sbase + (uint32_t)(c % 3) * GSTAGEB;
        const uint32_t sB = sA + GATILE;
#pragma unroll
        for (int kb = 0; kb < 4; kb++) {
            uint32_t a[4][4];
#pragma unroll
            for (int am = 0; am < 4; am++)
                ldmat4(a[am][0], a[am][1], a[am][2], a[am][3],
                       sA + (wm * 64 + am * 16 + lmrow) * GROWB + (kb * 2 + lmunit) * 16);
#pragma unroll
            for (int bb2 = 0; bb2 < 2; bb2++) {
                uint32_t r0, r1, r2, r3;
                ldmat4(r0, r1, r2, r3,
                       sB + (wn * 32 + bb2 * 16 + lmrow) * GROWB + (kb * 2 + lmunit) * 16);
#pragma unroll
                for (int am = 0; am < 4; am++) {
                    mma16816h(acc[am][bb2 * 2],     a[am][0], a[am][1], a[am][2], a[am][3], r0, r2);
                    mma16816h(acc[am][bb2 * 2 + 1], a[am][0], a[am][1], a[am][2], a[am][3], r1, r3);
                }
            }
        }
    }

    const int g = lane >> 2, it = lane & 3;
#pragma unroll
    for (int am = 0; am < 4; am++) {
        const int row0 = m0 + wm * 64 + am * 16 + g;
#pragma unroll
        for (int bn = 0; bn < 4; bn++) {
            const int col = n0 + wn * 32 + bn * 8 + it * 2;
            if (EP == 0) {
                float* p0 = (float*)OUT + (size_t)row0 * 1024 + col;
                float* p1 = p0 + 8 * 1024;
                *(float2*)p0 = make_float2(acc[am][bn][0], acc[am][bn][1]);
                *(float2*)p1 = make_float2(acc[am][bn][2], acc[am][bn][3]);
            } else {
                const int h = col >> 6, d = col & 63;
#pragma unroll
                for (int half_i = 0; half_i < 2; half_i++) {
                    __half2 hv = __floats2half2_rn(acc[am][bn][half_i * 2],
                                                   acc[am][bn][half_i * 2 + 1]);
                    __half* op = (__half*)OUT
                        + (size_t)(row0 + half_i * 8) * 1024 + h * 64 + d;
                    *(__half2*)op = hv;
                }
            }
        }
    }
}

// ================= HMMA flash attention (R14 config: double-buffered) =========
#define TROW 272
#define QSZ (128 * TROW)                 // 34816
#define KVSUB (64 * TROW)                // 17408
#define VROW 144
#define VSUB (64 * VROW)                 // 9216
#define KVSTRIDE (KVSUB + VSUB)          // 26624
#define ATTN_SMEM (QSZ + 2 * KVSTRIDE)   // 88064

__global__ __launch_bounds__(256, 2)
void attn_tc(const float* __restrict__ mask,
             const __nv_bfloat16* __restrict__ Q2,
             const __nv_bfloat16* __restrict__ K2,
             const __half* __restrict__ Vh,
             __half* __restrict__ Aout) {
    extern __shared__ __align__(128) char smc[];
    const uint32_t sq = smem_u32(smc);

    const int tid = threadIdx.x;
    const int wid = tid >> 5;
    const int lane = tid & 31;
    const int g = lane >> 2, it = lane & 3;
    const int lmrow = ((lane >> 3) & 1) * 8 + (lane & 7);
    const int lmunit = lane >> 4;

    const int b = blockIdx.z, h = blockIdx.y;
    const int q0 = blockIdx.x * 128;
    const size_t brow = (size_t)b * SS;

#pragma unroll
    for (int i = 0; i < 8; i++) {
        int idx = tid + i * 256;
        int u = idx & 15, r = idx >> 4;
        cp16(sq + r * TROW + u * 16, Q2 + (brow + q0 + r) * 2048 + h * 128 + u * 8);
    }
    cp_commit();

#pragma unroll
    for (int i = 0; i < 4; i++) {
        int idx = tid + i * 256;
        int u = idx & 15, r = idx >> 4;
        cp16(sq + QSZ + r * TROW + u * 16, K2 + (brow + r) * 2048 + h * 128 + u * 8);
    }
#pragma unroll
    for (int i = 0; i < 2; i++) {
        int idx = tid + i * 256;
        int u = idx & 7, r = idx >> 3;
        cp16(sq + QSZ + KVSUB + r * VROW + u * 16, Vh + (brow + r) * 1024 + h * 64 + u * 8);
    }
    cp_commit();

    float o[8][4];
#pragma unroll
    for (int dn = 0; dn < 8; dn++)
#pragma unroll
        for (int j = 0; j < 4; j++) o[dn][j] = 0.f;
    float mst0 = -INFINITY, mst1 = -INFINITY, l0 = 0.f, l1 = 0.f;

    const float* mrow0 = mask + ((size_t)b * SS + q0 + wid * 16 + g) * SS;
    const float* mrow1 = mrow0 + 8 * SS;

    uint32_t qh[4][4];
    bool qh_loaded = false;

    for (int st = 0; st < 32; st++) {
        const int cur = st & 1;
        cp_wait<0>();
        __syncthreads();

        if (st + 1 < 32) {
            const uint32_t kb = sq + QSZ + (uint32_t)(cur ^ 1) * KVSTRIDE;
            const size_t gbase = brow + (size_t)(st + 1) * 64;
#pragma unroll
            for (int i = 0; i < 4; i++) {
                int idx = tid + i * 256;
                int u = idx & 15, r = idx >> 4;
                cp16(kb + r * TROW + u * 16, K2 + (gbase + r) * 2048 + h * 128 + u * 8);
            }
#pragma unroll
            for (int i = 0; i < 2; i++) {
                int idx = tid + i * 256;
                int u = idx & 7, r = idx >> 3;
                cp16(kb + KVSUB + r * VROW + u * 16, Vh + (gbase + r) * 1024 + h * 64 + u * 8);
            }
            cp_commit();
        }

        if (!qh_loaded) {
            qh_loaded = true;
#pragma unroll
            for (int u4 = 0; u4 < 4; u4++)
                ldmat4(qh[u4][0], qh[u4][1], qh[u4][2], qh[u4][3],
                       sq + (wid * 16 + lmrow) * TROW + (u4 * 2 + lmunit) * 16);
        }

        const uint32_t sk = sq + QSZ + (uint32_t)cur * KVSTRIDE;
        const uint32_t sv = sk + KVSUB;

        float s[8][4];
#pragma unroll
        for (int nb = 0; nb < 8; nb++)
#pragma unroll
            for (int j = 0; j < 4; j++) s[nb][j] = 0.f;

#pragma unroll
        for (int u4 = 0; u4 < 4; u4++) {
            uint32_t ql0, ql1, ql2, ql3;
            ldmat4(ql0, ql1, ql2, ql3,
                   sq + (wid * 16 + lmrow) * TROW + (8 + u4 * 2 + lmunit) * 16);
#pragma unroll
            for (int nb16 = 0; nb16 < 4; nb16++) {
                uint32_t r0, r1, r2, r3;
                ldmat4(r0, r1, r2, r3,
                       sk + (nb16 * 16 + lmrow) * TROW + (u4 * 2 + lmunit) * 16);
                mma16816(s[nb16 * 2],     qh[u4][0], qh[u4][1], qh[u4][2], qh[u4][3], r0, r2);
                mma16816(s[nb16 * 2 + 1], qh[u4][0], qh[u4][1], qh[u4][2], qh[u4][3], r1, r3);
                mma16816(s[nb16 * 2],     ql0, ql1, ql2, ql3, r0, r2);
                mma16816(s[nb16 * 2 + 1], ql0, ql1, ql2, ql3, r1, r3);
            }
#pragma unroll
            for (int nb16 = 0; nb16 < 4; nb16++) {
                uint32_t r0, r1, r2, r3;
                ldmat4(r0, r1, r2, r3,
                       sk + (nb16 * 16 + lmrow) * TROW + (8 + u4 * 2 + lmunit) * 16);
                mma16816(s[nb16 * 2],     qh[u4][0], qh[u4][1], qh[u4][2], qh[u4][3], r0, r2);
                mma16816(s[nb16 * 2 + 1], qh[u4][0], qh[u4][1], qh[u4][2], qh[u4][3], r1, r3);
            }
        }

        float mx0 = -INFINITY, mx1 = -INFINITY;
#pragma unroll
        for (int nb = 0; nb < 8; nb++) {
            const int col = st * 64 + nb * 8 + it * 2;
            float2 m0 = *(const float2*)(mrow0 + col);
            float2 m1 = *(const float2*)(mrow1 + col);
            s[nb][0] = fmaf(s[nb][0], 0.125f, m0.x);
            s[nb][1] = fmaf(s[nb][1], 0.125f, m0.y);
            s[nb][2] = fmaf(s[nb][2], 0.125f, m1.x);
            s[nb][3] = fmaf(s[nb][3], 0.125f, m1.y);
            mx0 = fmaxf(mx0, fmaxf(s[nb][0], s[nb][1]));
            mx1 = fmaxf(mx1, fmaxf(s[nb][2], s[nb][3]));
        }
        mx0 = fmaxf(mx0, __shfl_xor_sync(0xffffffffu, mx0, 1));
        mx0 = fmaxf(mx0, __shfl_xor_sync(0xffffffffu, mx0, 2));
        mx1 = fmaxf(mx1, __shfl_xor_sync(0xffffffffu, mx1, 1));
        mx1 = fmaxf(mx1, __shfl_xor_sync(0xffffffffu, mx1, 2));

        const float nm0 = fmaxf(mst0, mx0), nm1 = fmaxf(mst1, mx1);
        const float corr0 = __expf(mst0 - nm0), corr1 = __expf(mst1 - nm1);
        mst0 = nm0; mst1 = nm1;

        uint32_t ph[16];
        float sum0 = 0.f, sum1 = 0.f;
#pragma unroll
        for (int nb = 0; nb < 8; nb++) {
            float p0 = __expf(s[nb][0] - nm0);
            float p1 = __expf(s[nb][1] - nm0);
            float p2 = __expf(s[nb][2] - nm1);
            float p3 = __expf(s[nb][3] - nm1);
            sum0 += p0 + p1; sum1 += p2 + p3;
            const int u = nb >> 1;
            const int base = u * 4 + (nb & 1) * 2;
            ph[base]     = pack_h2(p0, p1);
            ph[base + 1] = pack_h2(p2, p3);
        }
        sum0 += __shfl_xor_sync(0xffffffffu, sum0, 1);
        sum0 += __shfl_xor_sync(0xffffffffu, sum0, 2);
        sum1 += __shfl_xor_sync(0xffffffffu, sum1, 1);
        sum1 += __shfl_xor_sync(0xffffffffu, sum1, 2);
        l0 = l0 * corr0 + sum0;
        l1 = l1 * corr1 + sum1;
#pragma unroll
        for (int dn = 0; dn < 8; dn++) {
            o[dn][0] *= corr0; o[dn][1] *= corr0;
            o[dn][2] *= corr1; o[dn][3] *= corr1;
        }

#pragma unroll
        for (int u = 0; u < 4; u++) {
            const uint32_t* ap = ph + u * 4;
#pragma unroll
            for (int dn16 = 0; dn16 < 4; dn16++) {
                uint32_t r0, r1, r2, r3;
                ldmat4t(r0, r1, r2, r3,
                        sv + (u * 16 + lmrow) * VROW + (dn16 * 2 + lmunit) * 16);
                mma16816h(o[dn16 * 2],     ap[0], ap[1], ap[2], ap[3], r0, r1);
                mma16816h(o[dn16 * 2 + 1], ap[0], ap[1], ap[2], ap[3], r2, r3);
            }
        }
    }

    const float inv0 = 1.f / l0, inv1 = 1.f / l1;
    const size_t row0 = brow + q0 + wid * 16 + g;
#pragma unroll
    for (int dn = 0; dn < 8; dn++) {
        const int col = h * 64 + dn * 8 + it * 2;
        __half2 a01 = __floats2half2_rn(o[dn][0] * inv0, o[dn][1] * inv0);
        __half2 a23 = __floats2half2_rn(o[dn][2] * inv1, o[dn][3] * inv1);
        *(__half2*)(Aout + row0 * 1024 + col) = a01;
        *(__half2*)(Aout + (row0 + 8) * 1024 + col) = a23;
    }
}

// ---------------- launch ----------------
extern "C" void kernel_launch(void* const* d_in, const int* in_sizes, int n_in,
                              void* d_out, int out_size) {
    (void)in_sizes; (void)n_in; (void)out_size;
    const float* hidden = (const float*)d_in[0];
    const float* mask   = (const float*)d_in[1];
    const float* qs = (const float*)d_in[2];
    const float* qd = (const float*)d_in[3];
    const float* ks = (const float*)d_in[4];
    const float* kd = (const float*)d_in[5];
    const float* vs = (const float*)d_in[6];
    const float* vd = (const float*)d_in[7];
    const float* os = (const float*)d_in[8];
    const float* od = (const float*)d_in[9];

    __nv_bfloat16 *a2, *wq2, *wk2, *q2, *k2;
    __half *ah, *wvh, *woh, *vh;
    cudaGetSymbolAddress((void**)&a2,  g_a2);
    cudaGetSymbolAddress((void**)&ah,  g_ah);
    cudaGetSymbolAddress((void**)&wq2, g_wq2);
    cudaGetSymbolAddress((void**)&wk2, g_wk2);
    cudaGetSymbolAddress((void**)&wvh, g_wvh);
    cudaGetSymbolAddress((void**)&woh, g_woh);
    cudaGetSymbolAddress((void**)&q2,  g_q2);
    cudaGetSymbolAddress((void**)&k2,  g_k2);
    cudaGetSymbolAddress((void**)&vh,  g_vh);

    cudaFuncSetAttribute(tc_gemm, cudaFuncAttributeMaxDynamicSharedMemorySize, GSMEM);
    cudaFuncSetAttribute(tc_gemm_h<0>, cudaFuncAttributeMaxDynamicSharedMemorySize, GSMEM);
    cudaFuncSetAttribute(tc_gemm_h<1>, cudaFuncAttributeMaxDynamicSharedMemorySize, GSMEM);
    cudaFuncSetAttribute(attn_tc, cudaFuncAttributeMaxDynamicSharedMemorySize, ATTN_SMEM);

    // fused prep (balanced grid)
    prep_kernel<<<dim3(1024, 8), 256>>>(hidden, qs, qd, ks, kd, vs, vd, os, od,
                                        a2, ah, wq2, wk2, wvh, woh);

    // Q,K projections (bf16 3-term)
    tc_gemm<<<dim3(8, 16, 2), 512, GSMEM>>>(a2, wq2, wk2, q2, k2);

    // V projection (fp16 2-term) -> per-head fp16
    tc_gemm_h<1><<<dim3(8, 16, 1), 512, GSMEM>>>(ah, wvh, vh);

    // attention -> fp16 single output into g_ah (reused)
    attn_tc<<<dim3(SS / 128, NHH, BB), 256, ATTN_SMEM>>>(mask, q2, k2, vh, ah);

    // O projection (fp16 2-term) -> fp32 d_out
    tc_gemm_h<0><<<dim3(8, 16, 1), 512, GSMEM>>>(ah, woh, (float*)d_out);
}